// round 9
// baseline (speedup 1.0000x reference)
#include <cuda_runtime.h>
#include <cstdint>

#define Bz   256
#define Tz   512
#define Ez   200
#define Hz   100
#define NCz  5
#define BT   131072      // B*T

typedef unsigned long long ull;

// ---------------- scratch ----------------
__device__ float g_scale[BT];
__device__ float g_xp[(size_t)BT * 300];   // 157 MB
__device__ float g_state[Bz * Hz];

// ---------------- helpers ----------------
__device__ __forceinline__ float sigf(float x) {
    return 1.0f / (1.0f + __expf(-x));
}
__device__ __forceinline__ float tanh_fast(float x) {
    float t = __expf(-2.0f * fabsf(x));
    float r = (1.0f - t) / (1.0f + t);
    return copysignf(r, x);
}
__device__ __forceinline__ float to_tf32(float x) {
    uint32_t u;
    asm("cvt.rna.tf32.f32 %0, %1;" : "=r"(u) : "f"(x));
    return __uint_as_float(u);
}
__device__ __forceinline__ void fma2(ull& d, ull a, ull b) {
    asm("fma.rn.f32x2 %0, %1, %2, %0;" : "+l"(d) : "l"(a), "l"(b));
}
__device__ __forceinline__ float upksum(ull v) {
    float lo, hi;
    asm("mov.b64 {%0,%1}, %2;" : "=f"(lo), "=f"(hi) : "l"(v));
    return lo + hi;
}

// ---------------- K1: per-row embedding norm scale ----------------
__global__ void __launch_bounds__(256) scale_kernel(const int* __restrict__ txt,
                                                    const float* __restrict__ emb) {
    int warp = (blockIdx.x * 256 + threadIdx.x) >> 5;
    int lane = threadIdx.x & 31;
    if (warp >= BT) return;
    int tok = txt[warp];
    const float* row = emb + (size_t)tok * Ez;
    float ss = 0.f;
    for (int k = lane; k < Ez; k += 32) { float v = row[k]; ss += v * v; }
    #pragma unroll
    for (int o = 16; o > 0; o >>= 1) ss += __shfl_xor_sync(0xffffffffu, ss, o);
    if (lane == 0) {
        float n = sqrtf(ss);
        g_scale[warp] = (n > 1.0f) ? 1.0f / (n + 1e-7f) : 1.0f;
    }
}

// ---------------- dummy (shifts ncu capture slot onto the fused kernel) ----------------
__global__ void dummy_kernel() {}

// ---------------- K2: tf32 MMA GEMM (xp = norm(emb[txt]) @ W_ih^T + b_ih) ----------------
template <int KDIM, int KCEIL, int KSTR, int TN, int WNc, bool GATHER>
__global__ void __launch_bounds__(256) mma_gemm_kernel(
    const float* __restrict__ Ain,
    const int* __restrict__ txt,
    const float* __restrict__ emb,
    const float* __restrict__ W,
    const float* __restrict__ bias,
    float* __restrict__ C,
    int NV)
{
    extern __shared__ float sm[];
    float* As = sm;
    float* Bs = sm + 64 * KSTR;
    __shared__ int   s_tok[64];
    __shared__ float s_scl[64];

    const int tid   = threadIdx.x;
    const int rbase = blockIdx.x * 64;
    const int nbase = blockIdx.y * TN;

    if (GATHER) {
        if (tid < 64) {
            int r = rbase + tid;
            s_tok[tid] = txt[r];
            s_scl[tid] = g_scale[r];
        }
        __syncthreads();
    }

    const int K4 = KCEIL / 4;
    for (int e = tid; e < 64 * K4; e += 256) {
        int row = e / K4, k4 = e % K4;
        float4 v = make_float4(0.f, 0.f, 0.f, 0.f);
        if (4 * k4 + 3 < KDIM) {
            if (GATHER) {
                const float4* p = (const float4*)(emb + (size_t)s_tok[row] * KDIM) + k4;
                v = *p;
                float s = s_scl[row];
                v.x *= s; v.y *= s; v.z *= s; v.w *= s;
            } else {
                const float4* p = (const float4*)(Ain + (size_t)(rbase + row) * KDIM) + k4;
                v = *p;
            }
        }
        float4 o = make_float4(to_tf32(v.x), to_tf32(v.y), to_tf32(v.z), to_tf32(v.w));
        *(float4*)(As + row * KSTR + 4 * k4) = o;
    }
    for (int e = tid; e < TN * K4; e += 256) {
        int n = e / K4, k4 = e % K4;
        int ng = nbase + n;
        float4 v = make_float4(0.f, 0.f, 0.f, 0.f);
        if (ng < NV && 4 * k4 + 3 < KDIM) {
            const float4* p = (const float4*)(W + (size_t)ng * KDIM) + k4;
            v = *p;
        }
        float4 o = make_float4(to_tf32(v.x), to_tf32(v.y), to_tf32(v.z), to_tf32(v.w));
        *(float4*)(Bs + n * KSTR + 4 * k4) = o;
    }
    __syncthreads();

    const int wid  = tid >> 5;
    const int lane = tid & 31;
    const int g    = lane >> 2;
    const int tg   = lane & 3;
    const int mwarp = wid & 1;
    const int nwarp = wid >> 1;
    const int NF = WNc / 8;

    float c[2][NF][4];
    #pragma unroll
    for (int mt = 0; mt < 2; mt++)
        #pragma unroll
        for (int nf = 0; nf < NF; nf++)
            #pragma unroll
            for (int i = 0; i < 4; i++) c[mt][nf][i] = 0.f;

    const float* Aw = As + (mwarp * 32) * KSTR;
    const float* Bw = Bs + (nwarp * WNc) * KSTR;

    #pragma unroll 1
    for (int k8 = 0; k8 < KCEIL / 8; k8++) {
        int k0 = k8 * 8;
        uint32_t a[2][4], b[NF][2];
        #pragma unroll
        for (int mt = 0; mt < 2; mt++) {
            const float* ap = Aw + (mt * 16 + g) * KSTR + k0 + tg;
            a[mt][0] = __float_as_uint(ap[0]);
            a[mt][1] = __float_as_uint(ap[8 * KSTR]);
            a[mt][2] = __float_as_uint(ap[4]);
            a[mt][3] = __float_as_uint(ap[8 * KSTR + 4]);
        }
        #pragma unroll
        for (int nf = 0; nf < NF; nf++) {
            const float* bp = Bw + (nf * 8 + g) * KSTR + k0 + tg;
            b[nf][0] = __float_as_uint(bp[0]);
            b[nf][1] = __float_as_uint(bp[4]);
        }
        #pragma unroll
        for (int mt = 0; mt < 2; mt++)
            #pragma unroll
            for (int nf = 0; nf < NF; nf++) {
                asm volatile(
                    "mma.sync.aligned.m16n8k8.row.col.f32.tf32.tf32.f32 "
                    "{%0,%1,%2,%3}, {%4,%5,%6,%7}, {%8,%9}, {%0,%1,%2,%3};"
                    : "+f"(c[mt][nf][0]), "+f"(c[mt][nf][1]),
                      "+f"(c[mt][nf][2]), "+f"(c[mt][nf][3])
                    : "r"(a[mt][0]), "r"(a[mt][1]), "r"(a[mt][2]), "r"(a[mt][3]),
                      "r"(b[nf][0]), "r"(b[nf][1]));
            }
    }

    #pragma unroll
    for (int mt = 0; mt < 2; mt++) {
        int row = rbase + mwarp * 32 + mt * 16 + g;
        #pragma unroll
        for (int nf = 0; nf < NF; nf++) {
            int col = nbase + nwarp * WNc + nf * 8 + 2 * tg;
            if (col < NV) {
                float b0 = bias[col], b1 = bias[col + 1];
                float2 v0 = make_float2(c[mt][nf][0] + b0, c[mt][nf][1] + b1);
                float2 v1 = make_float2(c[mt][nf][2] + b0, c[mt][nf][3] + b1);
                *(float2*)(C + (size_t)row * NV + col) = v0;
                *(float2*)(C + (size_t)(row + 8) * NV + col) = v1;
            }
        }
    }
}

// ============================================================================
// Fused scan v3b: k-split pair GEMV. 128 blocks (2 batches), 1024 threads
// (64-reg cap -> 25-ull weight array stays resident, no hot spill):
//   tid 0-999 : GEMV, row r = tid>>1, half = tid&1 (k-range half*50..half*50+49)
//       r <300 : W_hh row (GRU pre-act),  src hb
//       r <400 : W_ti row (ti),           src hb
//       r <500 : W_ts row (m),            src stb
//     pair combined with one shfl_down; even lane stores outp[b][r] (+bias).
//   warp 31 lanes 8-31 : z/li/pg reductions (scalars held by lane 8 = tid 1000).
//   phase 2: tid<100 h-update; 100-199 st-update; 200-299 x prefetch.
// ============================================================================
__global__ void __launch_bounds__(1024, 1) fused_scan_kernel(
    const float* __restrict__ Whh, const float* __restrict__ bhh,
    const float* __restrict__ Wts, const float* __restrict__ bts,
    const float* __restrict__ Wti, const float* __restrict__ bti,
    const float* __restrict__ Wlgr, const float* __restrict__ blgr,
    const int* __restrict__ lens)
{
    __shared__ __align__(16) float hb[2][2][104];    // h double buffer
    __shared__ __align__(16) float stb[2][2][104];   // st double buffer
    __shared__ float outp[2][512];                   // GEMV outputs [batch][row]
    __shared__ float xbuf[2][2][304];                // x double buffer
    __shared__ float wlgr_s[100], wl_s[100];
    __shared__ float redpart[24][8];
    __shared__ float redv[4];                        // z0,z1,g0,g1

    const int tid = threadIdx.x;
    const int b0 = blockIdx.x * 2;
    const float* xp0 = g_xp + (size_t)b0 * Tz * 300;
    const float* xp1 = xp0 + (size_t)Tz * 300;

    const int  r    = tid >> 1;
    const int  half = tid & 1;
    const int  wid  = tid >> 5;
    const int  lane = tid & 31;
    const bool isG   = (tid < 1000);
    const bool isRed = (wid == 31 && lane >= 8);

    // ---- init shared ----
    if (tid < 104) {
        hb[0][0][tid] = 0.f;  hb[0][1][tid] = 0.f;
        hb[1][0][tid] = 0.f;  hb[1][1][tid] = 0.f;
        stb[0][0][tid] = 0.f; stb[0][1][tid] = 0.f;
        stb[1][0][tid] = 0.f; stb[1][1][tid] = 0.f;
    }
    if (tid >= 104 && tid < 204) {
        int k = tid - 104;
        wlgr_s[k] = Wlgr[k];
        wl_s[k]   = Wlgr[100 + k];
    }

    // ---- GEMV weight setup (permuted: 1 ull + 12 ulonglong2 uniform pattern) ----
    ull wS = 0ull, wV[24];
    float bias_r = 0.f;   // only meaningful on even lanes (added after pair-sum)
    const ull* srcBase = nullptr;   // &buf[0][0][half*50] as ull*
    int ullOff = 0, v2Off = 0;
    const ull* hbu  = (const ull*)&hb[0][0][0];
    const ull* stbu = (const ull*)&stb[0][0][0];
    if (isG) {
        const float* wsrc;
        float bsel = 0.f;
        if (r < 300)      { wsrc = Whh + r * 100;         bsel = bhh[r]; }
        else if (r < 400) { wsrc = Wti + (r - 300) * 100; bsel = bti[r - 300]; }
        else              { wsrc = Wts + (r - 400) * 100; bsel = 0.f; }
        const ull* p = (const ull*)(wsrc + half * 50);    // 25 ulls
        if (half == 0) {
            wS = p[24];
            #pragma unroll
            for (int q = 0; q < 24; q++) wV[q] = p[q];
            ullOff = 24; v2Off = 0;
            bias_r = bsel;
        } else {
            wS = p[0];
            #pragma unroll
            for (int q = 0; q < 24; q++) wV[q] = p[1 + q];
            ullOff = 0; v2Off = 1;
        }
        srcBase = ((r < 400) ? hbu : stbu) + half * 25;
    }
    // st-update threads need bts; x prefetch prologue
    float bts_r = 0.f;
    if (tid >= 100 && tid < 200) bts_r = bts[tid - 100];
    if (tid >= 200 && tid < 300) {
        int j = tid - 200;
        xbuf[0][0][j]       = xp0[j];        xbuf[0][1][j]       = xp1[j];
        xbuf[0][0][100 + j] = xp0[100 + j];  xbuf[0][1][100 + j] = xp1[100 + j];
        xbuf[0][0][200 + j] = xp0[200 + j];  xbuf[0][1][200 + j] = xp1[200 + j];
    }
    int slen0 = 0, slen1 = 0; float blg = 0.f;
    if (tid == 1000) { slen0 = lens[b0]; slen1 = lens[b0 + 1]; blg = blgr[0]; }
    const uint32_t pmask = (wid == 31) ? 0x000000FFu : 0xFFFFFFFFu;
    __syncthreads();

    for (int s = 0; s <= Tz; s++) {
        const int pp = (s & 1) ^ 1;          // parity holding h_{s-1} / st_{s-2}
        const int pc = s & 1;

        // ================= phase 1 =================
        if (isG) {
            const ull* H0 = srcBase + pp * 104;
            ull aA = 0ull, aB = 0ull;
            fma2(aA, wS, H0[ullOff]);
            const ulonglong2* HV = (const ulonglong2*)(H0 + v2Off);
            #pragma unroll
            for (int q = 0; q < 12; q++) {
                ulonglong2 h = HV[q];
                fma2(aA, wV[2 * q],     h.x);
                fma2(aB, wV[2 * q + 1], h.y);
            }
            float o0 = upksum(aA) + upksum(aB);
            const ull* H1 = H0 + 52;
            aA = 0ull; aB = 0ull;
            fma2(aA, wS, H1[ullOff]);
            const ulonglong2* HV1 = (const ulonglong2*)(H1 + v2Off);
            #pragma unroll
            for (int q = 0; q < 12; q++) {
                ulonglong2 h = HV1[q];
                fma2(aA, wV[2 * q],     h.x);
                fma2(aB, wV[2 * q + 1], h.y);
            }
            float o1 = upksum(aA) + upksum(aB);
            o0 += __shfl_down_sync(pmask, o0, 1);
            o1 += __shfl_down_sync(pmask, o1, 1);
            if (half == 0) {
                outp[0][r] = o0 + bias_r;
                outp[1][r] = o1 + bias_r;
            }
        } else if (isRed && s >= 1) {
            int k0 = lane - 8;               // 0..23
            float p0 = 0.f, p1 = 0.f, p2 = 0.f, p3 = 0.f;
            float p4 = 0.f, p5 = 0.f, p6 = 0.f, p7 = 0.f;
            for (int k = k0; k < 100; k += 24) {
                float h0 = hb[pp][0][k], h1 = hb[pp][1][k];
                float wg = wlgr_s[k], wl = wl_s[k];
                p0 += h0; p1 += h0 * h0; p2 += h0 * wg;
                p3 += h1; p4 += h1 * h1; p5 += h1 * wg;
                p6 += wl * stb[pp][0][k];
                p7 += wl * stb[pp][1][k];
            }
            redpart[k0][0] = p0; redpart[k0][1] = p1; redpart[k0][2] = p2;
            redpart[k0][3] = p3; redpart[k0][4] = p4; redpart[k0][5] = p5;
            redpart[k0][6] = p6; redpart[k0][7] = p7;
            __syncwarp(0xFFFFFF00u);
            if (k0 == 0) {
                float t0 = 0.f, t1 = 0.f, t2 = 0.f, t3 = 0.f;
                float t4 = 0.f, t5 = 0.f, t6 = 0.f, t7 = 0.f;
                #pragma unroll
                for (int i = 0; i < 24; i++) {
                    t0 += redpart[i][0]; t1 += redpart[i][1]; t2 += redpart[i][2];
                    t3 += redpart[i][3]; t4 += redpart[i][4]; t5 += redpart[i][5];
                    t6 += redpart[i][6]; t7 += redpart[i][7];
                }
                int t = s - 1;
                float att0 = 0.001f * t0 / fmaxf(sqrtf(t1), 1e-12f);
                float att1 = 0.001f * t3 / fmaxf(sqrtf(t4), 1e-12f);
                redv[0] = (t < slen0 && att0 > 0.f) ? att0 : 0.f;
                redv[1] = (t < slen1 && att1 > 0.f) ? att1 : 0.f;
                redv[2] = sigf(t2 + t6 + blg);
                redv[3] = sigf(t5 + t7 + blg);
            }
        }
        __syncthreads();

        // ================= phase 2 =================
        if (tid < 100) {
            if (s < Tz) {                    // GRU h-update, row tid
                int j = tid;
                float hr0 = outp[0][j], hz0 = outp[0][100 + j], hn0 = outp[0][200 + j];
                float hr1 = outp[1][j], hz1 = outp[1][100 + j], hn1 = outp[1][200 + j];
                float xr0 = xbuf[pc][0][j],       xr1 = xbuf[pc][1][j];
                float xz0 = xbuf[pc][0][100 + j], xz1 = xbuf[pc][1][100 + j];
                float xn0 = xbuf[pc][0][200 + j], xn1 = xbuf[pc][1][200 + j];
                float ho0 = hb[pp][0][j], ho1 = hb[pp][1][j];
                float r0 = sigf(xr0 + hr0), r1 = sigf(xr1 + hr1);
                float z0 = sigf(xz0 + hz0), z1 = sigf(xz1 + hz1);
                float n0 = tanh_fast(xn0 + r0 * hn0);
                float n1 = tanh_fast(xn1 + r1 * hn1);
                hb[pc][0][j] = (1.f - z0) * n0 + z0 * ho0;
                hb[pc][1][j] = (1.f - z1) * n1 + z1 * ho1;
            }
        } else if (tid < 200) {
            if (s >= 1) {                    // rec state update, t = s-1
                int j = tid - 100;
                float ti0 = outp[0][300 + j], ti1 = outp[1][300 + j];
                float m0  = outp[0][400 + j], m1  = outp[1][400 + j];
                float z0 = redv[0], z1 = redv[1];
                float g0 = redv[2], g1 = redv[3];
                float so0 = stb[pp][0][j], so1 = stb[pp][1][j];
                float ns0 = tanh_fast(ti0 + g0 * m0 + bts_r);
                float ns1 = tanh_fast(ti1 + g1 * m1 + bts_r);
                stb[pc][0][j] = (1.f - z0) * so0 + z0 * ns0;
                stb[pc][1][j] = (1.f - z1) * so1 + z1 * ns1;
            }
        } else if (tid < 300) {
            if (s <= Tz - 2) {               // prefetch x_{s+1}
                int j = tid - 200;
                const float* q0 = xp0 + (size_t)(s + 1) * 300;
                const float* q1 = xp1 + (size_t)(s + 1) * 300;
                int px = (s + 1) & 1;
                xbuf[px][0][j]       = q0[j];        xbuf[px][1][j]       = q1[j];
                xbuf[px][0][100 + j] = q0[100 + j];  xbuf[px][1][100 + j] = q1[100 + j];
                xbuf[px][0][200 + j] = q0[200 + j];  xbuf[px][1][200 + j] = q1[200 + j];
            }
        }
        __syncthreads();
    }

    // last st write was at s=Tz into parity 0
    if (tid >= 100 && tid < 200) {
        int j = tid - 100;
        g_state[b0 * Hz + j]       = stb[0][0][j];
        g_state[(b0 + 1) * Hz + j] = stb[0][1][j];
    }
}

// ---------------- K7: output projection ----------------
__global__ void __launch_bounds__(256) out_kernel(const float* __restrict__ Wout,
                                                  const float* __restrict__ bout,
                                                  float* __restrict__ out) {
    int idx = blockIdx.x * 256 + threadIdx.x;
    if (idx >= Bz * NCz) return;
    int b = idx / NCz, c = idx % NCz;
    float acc = bout[c];
    const float* s = g_state + b * Hz;
    const float* wr = Wout + c * Hz;
    #pragma unroll
    for (int k = 0; k < Hz; k++) acc += s[k] * wr[k];
    out[idx] = acc;
}

// ---------------- launch ----------------
extern "C" void kernel_launch(void* const* d_in, const int* in_sizes, int n_in,
                              void* d_out, int out_size) {
    const int*   txt   = (const int*)d_in[0];
    const int*   lens  = (const int*)d_in[1];
    const float* emb   = (const float*)d_in[2];
    const float* W_ih  = (const float*)d_in[3];
    const float* W_hh  = (const float*)d_in[4];
    const float* b_ih  = (const float*)d_in[5];
    const float* b_hh  = (const float*)d_in[6];
    const float* W_lgr = (const float*)d_in[7];
    const float* b_lgr = (const float*)d_in[8];
    const float* W_ts  = (const float*)d_in[9];
    const float* b_ts  = (const float*)d_in[10];
    const float* W_ti  = (const float*)d_in[11];
    const float* b_ti  = (const float*)d_in[12];
    const float* W_out = (const float*)d_in[13];
    const float* b_out = (const float*)d_in[14];
    float* out = (float*)d_out;

    float* xp = nullptr; cudaGetSymbolAddress((void**)&xp, g_xp);

    scale_kernel<<<BT / 8, 256>>>(txt, emb);

    {
        constexpr int SMEM = (64 + 160) * 204 * 4;
        cudaFuncSetAttribute((const void*)mma_gemm_kernel<200, 200, 204, 160, 40, true>,
                             cudaFuncAttributeMaxDynamicSharedMemorySize, SMEM);
        dim3 grid(BT / 64, 2);
        mma_gemm_kernel<200, 200, 204, 160, 40, true><<<grid, 256, SMEM>>>(
            nullptr, txt, emb, W_ih, b_ih, xp, 300);
    }

    // dummy: shifts the fused kernel into ncu's captured launch slot (#6 overall)
    dummy_kernel<<<1, 32>>>();

    fused_scan_kernel<<<Bz / 2, 1024>>>(W_hh, b_hh, W_ts, b_ts, W_ti, b_ti,
                                        W_lgr, b_lgr, lens);

    out_kernel<<<(Bz * NCz + 255) / 256, 256>>>(W_out, b_out, out);
}

// round 10
// speedup vs baseline: 1.5131x; 1.5131x over previous
#include <cuda_runtime.h>
#include <cstdint>

#define Bz   256
#define Tz   512
#define Ez   200
#define Hz   100
#define NCz  5
#define BT   131072      // B*T

typedef unsigned long long ull;

// ---------------- scratch ----------------
__device__ float g_scale[BT];
__device__ float g_xp[(size_t)BT * 300];   // 157 MB
__device__ float g_rnn[(size_t)BT * 100];  // 52 MB
__device__ float g_ti[(size_t)BT * 100];   // 52 MB
__device__ float g_z[BT];
__device__ float g_li[BT];
__device__ float g_state[Bz * Hz];

// ---------------- helpers ----------------
__device__ __forceinline__ float sigf(float x) {
    return 1.0f / (1.0f + __expf(-x));
}
__device__ __forceinline__ float tanh_fast(float x) {
    float t = __expf(-2.0f * fabsf(x));
    float r = (1.0f - t) / (1.0f + t);
    return copysignf(r, x);
}
__device__ __forceinline__ float to_tf32(float x) {
    uint32_t u;
    asm("cvt.rna.tf32.f32 %0, %1;" : "=r"(u) : "f"(x));
    return __uint_as_float(u);
}
__device__ __forceinline__ void fma2(ull& d, ull a, ull b) {
    asm("fma.rn.f32x2 %0, %1, %2, %0;" : "+l"(d) : "l"(a), "l"(b));
}
__device__ __forceinline__ float upksum(ull v) {
    float lo, hi;
    asm("mov.b64 {%0,%1}, %2;" : "=f"(lo), "=f"(hi) : "l"(v));
    return lo + hi;
}

// ---------------- K1: per-row embedding norm scale ----------------
__global__ void __launch_bounds__(256) scale_kernel(const int* __restrict__ txt,
                                                    const float* __restrict__ emb) {
    int warp = (blockIdx.x * 256 + threadIdx.x) >> 5;
    int lane = threadIdx.x & 31;
    if (warp >= BT) return;
    int tok = txt[warp];
    const float* row = emb + (size_t)tok * Ez;
    float ss = 0.f;
    for (int k = lane; k < Ez; k += 32) { float v = row[k]; ss += v * v; }
    #pragma unroll
    for (int o = 16; o > 0; o >>= 1) ss += __shfl_xor_sync(0xffffffffu, ss, o);
    if (lane == 0) {
        float n = sqrtf(ss);
        g_scale[warp] = (n > 1.0f) ? 1.0f / (n + 1e-7f) : 1.0f;
    }
}

// ---------------- dummy (shifts ncu capture slot onto gru_kernel) ----------------
__global__ void dummy_kernel() {}

// ---------------- K2/K5: tf32 MMA GEMM ----------------
template <int KDIM, int KCEIL, int KSTR, int TN, int WNc, bool GATHER>
__global__ void __launch_bounds__(256) mma_gemm_kernel(
    const float* __restrict__ Ain,
    const int* __restrict__ txt,
    const float* __restrict__ emb,
    const float* __restrict__ W,
    const float* __restrict__ bias,
    float* __restrict__ C,
    int NV)
{
    extern __shared__ float sm[];
    float* As = sm;
    float* Bs = sm + 64 * KSTR;
    __shared__ int   s_tok[64];
    __shared__ float s_scl[64];

    const int tid   = threadIdx.x;
    const int rbase = blockIdx.x * 64;
    const int nbase = blockIdx.y * TN;

    if (GATHER) {
        if (tid < 64) {
            int r = rbase + tid;
            s_tok[tid] = txt[r];
            s_scl[tid] = g_scale[r];
        }
        __syncthreads();
    }

    const int K4 = KCEIL / 4;
    for (int e = tid; e < 64 * K4; e += 256) {
        int row = e / K4, k4 = e % K4;
        float4 v = make_float4(0.f, 0.f, 0.f, 0.f);
        if (4 * k4 + 3 < KDIM) {
            if (GATHER) {
                const float4* p = (const float4*)(emb + (size_t)s_tok[row] * KDIM) + k4;
                v = *p;
                float s = s_scl[row];
                v.x *= s; v.y *= s; v.z *= s; v.w *= s;
            } else {
                const float4* p = (const float4*)(Ain + (size_t)(rbase + row) * KDIM) + k4;
                v = *p;
            }
        }
        float4 o = make_float4(to_tf32(v.x), to_tf32(v.y), to_tf32(v.z), to_tf32(v.w));
        *(float4*)(As + row * KSTR + 4 * k4) = o;
    }
    for (int e = tid; e < TN * K4; e += 256) {
        int n = e / K4, k4 = e % K4;
        int ng = nbase + n;
        float4 v = make_float4(0.f, 0.f, 0.f, 0.f);
        if (ng < NV && 4 * k4 + 3 < KDIM) {
            const float4* p = (const float4*)(W + (size_t)ng * KDIM) + k4;
            v = *p;
        }
        float4 o = make_float4(to_tf32(v.x), to_tf32(v.y), to_tf32(v.z), to_tf32(v.w));
        *(float4*)(Bs + n * KSTR + 4 * k4) = o;
    }
    __syncthreads();

    const int wid  = tid >> 5;
    const int lane = tid & 31;
    const int g    = lane >> 2;
    const int tg   = lane & 3;
    const int mwarp = wid & 1;
    const int nwarp = wid >> 1;
    const int NF = WNc / 8;

    float c[2][NF][4];
    #pragma unroll
    for (int mt = 0; mt < 2; mt++)
        #pragma unroll
        for (int nf = 0; nf < NF; nf++)
            #pragma unroll
            for (int i = 0; i < 4; i++) c[mt][nf][i] = 0.f;

    const float* Aw = As + (mwarp * 32) * KSTR;
    const float* Bw = Bs + (nwarp * WNc) * KSTR;

    #pragma unroll 1
    for (int k8 = 0; k8 < KCEIL / 8; k8++) {
        int k0 = k8 * 8;
        uint32_t a[2][4], b[NF][2];
        #pragma unroll
        for (int mt = 0; mt < 2; mt++) {
            const float* ap = Aw + (mt * 16 + g) * KSTR + k0 + tg;
            a[mt][0] = __float_as_uint(ap[0]);
            a[mt][1] = __float_as_uint(ap[8 * KSTR]);
            a[mt][2] = __float_as_uint(ap[4]);
            a[mt][3] = __float_as_uint(ap[8 * KSTR + 4]);
        }
        #pragma unroll
        for (int nf = 0; nf < NF; nf++) {
            const float* bp = Bw + (nf * 8 + g) * KSTR + k0 + tg;
            b[nf][0] = __float_as_uint(bp[0]);
            b[nf][1] = __float_as_uint(bp[4]);
        }
        #pragma unroll
        for (int mt = 0; mt < 2; mt++)
            #pragma unroll
            for (int nf = 0; nf < NF; nf++) {
                asm volatile(
                    "mma.sync.aligned.m16n8k8.row.col.f32.tf32.tf32.f32 "
                    "{%0,%1,%2,%3}, {%4,%5,%6,%7}, {%8,%9}, {%0,%1,%2,%3};"
                    : "+f"(c[mt][nf][0]), "+f"(c[mt][nf][1]),
                      "+f"(c[mt][nf][2]), "+f"(c[mt][nf][3])
                    : "r"(a[mt][0]), "r"(a[mt][1]), "r"(a[mt][2]), "r"(a[mt][3]),
                      "r"(b[nf][0]), "r"(b[nf][1]));
            }
    }

    #pragma unroll
    for (int mt = 0; mt < 2; mt++) {
        int row = rbase + mwarp * 32 + mt * 16 + g;
        #pragma unroll
        for (int nf = 0; nf < NF; nf++) {
            int col = nbase + nwarp * WNc + nf * 8 + 2 * tg;
            if (col < NV) {
                float b0 = bias[col], b1 = bias[col + 1];
                float2 v0 = make_float2(c[mt][nf][0] + b0, c[mt][nf][1] + b1);
                float2 v1 = make_float2(c[mt][nf][2] + b0, c[mt][nf][3] + b1);
                *(float2*)(C + (size_t)row * NV + col) = v0;
                *(float2*)(C + (size_t)(row + 8) * NV + col) = v1;
            }
        }
    }
}

// ---------------- K3: GRU scan with FFMA2 (320 threads -> 204-reg budget) ----------------
// tid 0-299: W_hh row in w[50] ull regs; matvec via fma.rn.f32x2 on k-pairs.
// h stored per-batch contiguous (hsh[batch][104]) so quads load as ulonglong2.
// tid<100 also do the h-update (phase 2) + x prefetch (double-buffered in regs).
__global__ void __launch_bounds__(320, 1) gru_kernel(const float* __restrict__ Whh,
                                                     const float* __restrict__ bhh) {
    __shared__ __align__(16) float hsh[2][104];   // [batch][k], single buffer
    __shared__ float hp[2][304];                  // pre-activations [batch][row]
    const int tid = threadIdx.x;
    const int b0 = blockIdx.x * 2, b1 = b0 + 1;
    const float* x0 = g_xp + (size_t)b0 * Tz * 300;
    const float* x1 = g_xp + (size_t)b1 * Tz * 300;

    ull w[50];
    float bh = 0.f;
    if (tid < 300) {
        const ull* wp = (const ull*)(Whh + tid * 100);
        #pragma unroll
        for (int q = 0; q < 50; q++) w[q] = wp[q];
        bh = bhh[tid];
    }
    if (tid < 104) { hsh[0][tid] = 0.f; hsh[1][tid] = 0.f; }

    float xr0 = 0.f, xz0 = 0.f, xn0 = 0.f, xr1 = 0.f, xz1 = 0.f, xn1 = 0.f;
    if (tid < 100) {
        xr0 = x0[tid]; xz0 = x0[100 + tid]; xn0 = x0[200 + tid];
        xr1 = x1[tid]; xz1 = x1[100 + tid]; xn1 = x1[200 + tid];
    }
    __syncthreads();

    for (int t = 0; t < Tz; t++) {
        float nr0 = 0.f, nz0 = 0.f, nn0 = 0.f, nr1 = 0.f, nz1 = 0.f, nn1 = 0.f;
        if (tid < 100 && t + 1 < Tz) {           // issue x prefetch early
            const float* p0 = x0 + (size_t)(t + 1) * 300;
            const float* p1 = x1 + (size_t)(t + 1) * 300;
            nr0 = p0[tid]; nz0 = p0[100 + tid]; nn0 = p0[200 + tid];
            nr1 = p1[tid]; nz1 = p1[100 + tid]; nn1 = p1[200 + tid];
        }
        if (tid < 300) {
            ull aA = 0ull, aB = 0ull, cA = 0ull, cB = 0ull;
            const ulonglong2* H0 = (const ulonglong2*)&hsh[0][0];
            const ulonglong2* H1 = (const ulonglong2*)&hsh[1][0];
            #pragma unroll
            for (int v = 0; v < 25; v++) {
                ulonglong2 h = H0[v];
                fma2(aA, w[2 * v],     h.x);
                fma2(aB, w[2 * v + 1], h.y);
            }
            #pragma unroll
            for (int v = 0; v < 25; v++) {
                ulonglong2 h = H1[v];
                fma2(cA, w[2 * v],     h.x);
                fma2(cB, w[2 * v + 1], h.y);
            }
            hp[0][tid] = bh + upksum(aA) + upksum(aB);
            hp[1][tid] = bh + upksum(cA) + upksum(cB);
        }
        __syncthreads();
        if (tid < 100) {
            float hr0 = hp[0][tid], hz0 = hp[0][100 + tid], hn0 = hp[0][200 + tid];
            float hr1 = hp[1][tid], hz1 = hp[1][100 + tid], hn1 = hp[1][200 + tid];
            float ho0 = hsh[0][tid], ho1 = hsh[1][tid];
            float r0 = sigf(xr0 + hr0), r1 = sigf(xr1 + hr1);
            float z0 = sigf(xz0 + hz0), z1 = sigf(xz1 + hz1);
            float n0 = tanh_fast(xn0 + r0 * hn0);
            float n1 = tanh_fast(xn1 + r1 * hn1);
            float hx = (1.f - z0) * n0 + z0 * ho0;
            float hy = (1.f - z1) * n1 + z1 * ho1;
            hsh[0][tid] = hx;
            hsh[1][tid] = hy;
            g_rnn[((size_t)b0 * Tz + t) * Hz + tid] = hx;
            g_rnn[((size_t)b1 * Tz + t) * Hz + tid] = hy;
            xr0 = nr0; xz0 = nz0; xn0 = nn0;
            xr1 = nr1; xz1 = nz1; xn1 = nn1;
        }
        __syncthreads();
    }
}

// ---------------- K4: per-(b,t) z (attention gate) and lgr_in ----------------
__global__ void __launch_bounds__(256) zli_kernel(const float* __restrict__ Wlgr,
                                                  const int* __restrict__ lens) {
    int warp = (blockIdx.x * 256 + threadIdx.x) >> 5;
    int lane = threadIdx.x & 31;
    if (warp >= BT) return;
    int b = warp >> 9;
    int t = warp & (Tz - 1);
    const float* r = g_rnn + (size_t)warp * Hz;
    float s1 = 0.f, s2 = 0.f, s3 = 0.f;
    for (int k = lane; k < Hz; k += 32) {
        float v = r[k];
        s1 += v;
        s2 += v * v;
        s3 += v * Wlgr[k];
    }
    #pragma unroll
    for (int o = 16; o > 0; o >>= 1) {
        s1 += __shfl_xor_sync(0xffffffffu, s1, o);
        s2 += __shfl_xor_sync(0xffffffffu, s2, o);
        s3 += __shfl_xor_sync(0xffffffffu, s3, o);
    }
    if (lane == 0) {
        float nrm = sqrtf(s2);
        float att = 0.001f * s1 / fmaxf(nrm, 1e-12f);
        float zv = (t < lens[b] && att > 0.f) ? att : 0.f;
        g_z[warp]  = zv;
        g_li[warp] = s3;
    }
}

// ---------------- K6: second recurrence, FFMA2 + smem-resident li/z ----------------
// 160 threads (409-reg budget): tid<100 = W_ts row in 50 ull regs + ti prefetch
// + state update; warp 4 (tid 128-159) = pg reduction + gate.
__global__ void __launch_bounds__(160, 1) rec_kernel(const float* __restrict__ Wts,
                                                     const float* __restrict__ bts,
                                                     const float* __restrict__ Wlgr,
                                                     const float* __restrict__ blgr) {
    __shared__ __align__(16) float stsh[2][104];
    __shared__ float li_sh[2][Tz];
    __shared__ float z_sh[2][Tz];
    __shared__ float gz[4];   // g0,g1,z0,z1
    const int tid = threadIdx.x;
    const int b0 = blockIdx.x * 2, b1 = b0 + 1;
    const float* t0 = g_ti + (size_t)b0 * Tz * Hz;
    const float* t1 = g_ti + (size_t)b1 * Tz * Hz;

    // preload li/z for both batches (coalesced, once)
    for (int i = tid; i < Tz; i += 160) {
        li_sh[0][i] = g_li[(size_t)b0 * Tz + i];
        li_sh[1][i] = g_li[(size_t)b1 * Tz + i];
        z_sh[0][i]  = g_z[(size_t)b0 * Tz + i];
        z_sh[1][i]  = g_z[(size_t)b1 * Tz + i];
    }
    if (tid < 104) { stsh[0][tid] = 0.f; stsh[1][tid] = 0.f; }

    ull w[50];
    float btsr = 0.f, tv0 = 0.f, tv1 = 0.f;
    if (tid < 100) {
        const ull* wp = (const ull*)(Wts + tid * 100);
        #pragma unroll
        for (int q = 0; q < 50; q++) w[q] = wp[q];
        btsr = bts[tid];
        tv0 = t0[tid]; tv1 = t1[tid];
    }
    float wl4[4] = {0.f, 0.f, 0.f, 0.f};
    float blg = 0.f;
    const int lane = tid - 128;
    if (tid >= 128) {
        #pragma unroll
        for (int i = 0; i < 4; i++) {
            int k = lane + 32 * i;
            wl4[i] = (k < 100) ? Wlgr[100 + k] : 0.f;
        }
        blg = blgr[0];
    }
    __syncthreads();

    for (int t = 0; t < Tz; t++) {
        float m0 = 0.f, m1 = 0.f, tn0 = 0.f, tn1 = 0.f;
        if (tid < 100) {
            if (t + 1 < Tz) {
                tn0 = t0[(size_t)(t + 1) * Hz + tid];
                tn1 = t1[(size_t)(t + 1) * Hz + tid];
            }
            ull aA = 0ull, aB = 0ull, cA = 0ull, cB = 0ull;
            const ulonglong2* S0 = (const ulonglong2*)&stsh[0][0];
            const ulonglong2* S1 = (const ulonglong2*)&stsh[1][0];
            #pragma unroll
            for (int v = 0; v < 25; v++) {
                ulonglong2 s = S0[v];
                fma2(aA, w[2 * v],     s.x);
                fma2(aB, w[2 * v + 1], s.y);
            }
            #pragma unroll
            for (int v = 0; v < 25; v++) {
                ulonglong2 s = S1[v];
                fma2(cA, w[2 * v],     s.x);
                fma2(cB, w[2 * v + 1], s.y);
            }
            m0 = upksum(aA) + upksum(aB);
            m1 = upksum(cA) + upksum(cB);
        } else if (tid >= 128) {
            float pg0 = 0.f, pg1 = 0.f;
            #pragma unroll
            for (int i = 0; i < 4; i++) {
                int k = lane + 32 * i;
                if (k < 100) {
                    pg0 += wl4[i] * stsh[0][k];
                    pg1 += wl4[i] * stsh[1][k];
                }
            }
            #pragma unroll
            for (int o = 16; o > 0; o >>= 1) {
                pg0 += __shfl_xor_sync(0xffffffffu, pg0, o);
                pg1 += __shfl_xor_sync(0xffffffffu, pg1, o);
            }
            if (lane == 0) {
                gz[0] = sigf(li_sh[0][t] + pg0 + blg);
                gz[1] = sigf(li_sh[1][t] + pg1 + blg);
                gz[2] = z_sh[0][t];
                gz[3] = z_sh[1][t];
            }
        }
        __syncthreads();
        if (tid < 100) {
            float g0 = gz[0], g1 = gz[1], zz0 = gz[2], zz1 = gz[3];
            float s0 = stsh[0][tid], s1 = stsh[1][tid];
            float ns0 = tanh_fast(tv0 + g0 * m0 + btsr);
            float ns1 = tanh_fast(tv1 + g1 * m1 + btsr);
            stsh[0][tid] = (1.f - zz0) * s0 + zz0 * ns0;
            stsh[1][tid] = (1.f - zz1) * s1 + zz1 * ns1;
            tv0 = tn0; tv1 = tn1;
        }
        __syncthreads();
    }

    if (tid < 100) {
        g_state[b0 * Hz + tid] = stsh[0][tid];
        g_state[b1 * Hz + tid] = stsh[1][tid];
    }
}

// ---------------- K7: output projection ----------------
__global__ void __launch_bounds__(256) out_kernel(const float* __restrict__ Wout,
                                                  const float* __restrict__ bout,
                                                  float* __restrict__ out) {
    int idx = blockIdx.x * 256 + threadIdx.x;
    if (idx >= Bz * NCz) return;
    int b = idx / NCz, c = idx % NCz;
    float acc = bout[c];
    const float* s = g_state + b * Hz;
    const float* wr = Wout + c * Hz;
    #pragma unroll
    for (int k = 0; k < Hz; k++) acc += s[k] * wr[k];
    out[idx] = acc;
}

// ---------------- launch ----------------
extern "C" void kernel_launch(void* const* d_in, const int* in_sizes, int n_in,
                              void* d_out, int out_size) {
    const int*   txt   = (const int*)d_in[0];
    const int*   lens  = (const int*)d_in[1];
    const float* emb   = (const float*)d_in[2];
    const float* W_ih  = (const float*)d_in[3];
    const float* W_hh  = (const float*)d_in[4];
    const float* b_ih  = (const float*)d_in[5];
    const float* b_hh  = (const float*)d_in[6];
    const float* W_lgr = (const float*)d_in[7];
    const float* b_lgr = (const float*)d_in[8];
    const float* W_ts  = (const float*)d_in[9];
    const float* b_ts  = (const float*)d_in[10];
    const float* W_ti  = (const float*)d_in[11];
    const float* b_ti  = (const float*)d_in[12];
    const float* W_out = (const float*)d_in[13];
    const float* b_out = (const float*)d_in[14];
    float* out = (float*)d_out;

    float* xp  = nullptr; cudaGetSymbolAddress((void**)&xp,  g_xp);
    float* rnn = nullptr; cudaGetSymbolAddress((void**)&rnn, g_rnn);
    float* ti  = nullptr; cudaGetSymbolAddress((void**)&ti,  g_ti);

    scale_kernel<<<BT / 8, 256>>>(txt, emb);

    {
        constexpr int SMEM = (64 + 160) * 204 * 4;
        cudaFuncSetAttribute((const void*)mma_gemm_kernel<200, 200, 204, 160, 40, true>,
                             cudaFuncAttributeMaxDynamicSharedMemorySize, SMEM);
        dim3 grid(BT / 64, 2);
        mma_gemm_kernel<200, 200, 204, 160, 40, true><<<grid, 256, SMEM>>>(
            nullptr, txt, emb, W_ih, b_ih, xp, 300);
    }

    // dummy: keeps ncu's capture slot (#4 of our launches) on gru_kernel
    dummy_kernel<<<1, 32>>>();

    gru_kernel<<<Bz / 2, 320>>>(W_hh, b_hh);

    zli_kernel<<<BT / 8, 256>>>(W_lgr, lens);

    {
        constexpr int SMEM = (64 + 128) * 108 * 4;
        cudaFuncSetAttribute((const void*)mma_gemm_kernel<100, 104, 108, 128, 32, false>,
                             cudaFuncAttributeMaxDynamicSharedMemorySize, SMEM);
        dim3 grid(BT / 64, 1);
        mma_gemm_kernel<100, 104, 108, 128, 32, false><<<grid, 256, SMEM>>>(
            rnn, nullptr, nullptr, W_ti, b_ti, ti, 100);
    }

    rec_kernel<<<Bz / 2, 160>>>(W_ts, b_ts, W_lgr, b_lgr);

    out_kernel<<<(Bz * NCz + 255) / 256, 256>>>(W_out, b_out, out);
}